// round 5
// baseline (speedup 1.0000x reference)
#include <cuda_runtime.h>
#include <cstdint>

#define QN    1024
#define NDATA 50000
#define DIM   512
#define KNN   10

#define BM 128
#define BN 128
#define BK 16

// Scratch (allocation-free rule: __device__ globals)
__device__ float g_scores[(size_t)QN * NDATA];   // ~204.8 MB
__device__ float g_d2[NDATA];
__device__ int   g_t64;                          // 1 if targets stored as int64

// ---------------------------------------------------------------------------
// Kernel 0: probe targets dtype. If the first 64 values interpreted as int64
// all lie in [0, 100), storage is int64 (false-positive prob with int32
// storage: 0.01^64). Deterministic; runs every launch.
// ---------------------------------------------------------------------------
__global__ void probe_targets(const void* __restrict__ targets) {
    if (threadIdx.x == 0) {
        const long long* t = (const long long*)targets;
        int ok = 1;
        for (int i = 0; i < 64; i++) {
            long long v = t[i];
            if (v < 0 || v >= 100) { ok = 0; break; }
        }
        g_t64 = ok;
    }
}

// ---------------------------------------------------------------------------
// Kernel 1: d2[n] = ||data[n]||^2   (one warp per row)
// ---------------------------------------------------------------------------
__global__ void d2_kernel(const float* __restrict__ data) {
    int warp = (blockIdx.x * blockDim.x + threadIdx.x) >> 5;
    int lane = threadIdx.x & 31;
    if (warp >= NDATA) return;
    const float4* row = (const float4*)(data + (size_t)warp * DIM);
    float acc = 0.f;
#pragma unroll
    for (int i = 0; i < DIM / 4 / 32; i++) {
        float4 v = row[lane + i * 32];
        acc += v.x * v.x + v.y * v.y + v.z * v.z + v.w * v.w;
    }
#pragma unroll
    for (int o = 16; o > 0; o >>= 1) acc += __shfl_down_sync(0xffffffffu, acc, o);
    if (lane == 0) g_d2[warp] = acc;
}

// ---------------------------------------------------------------------------
// Kernel 2: scores[m][n] = d2[n] - 2 * dot(X[m], data[n])
// Classic 128x128x16 fp32 tiled GEMM, 256 threads, 8x8 microtile.
// Ordering of scores == ordering of reference distances per query
// (x^2 constant per row, sqrt monotone, clamp never active).
// ---------------------------------------------------------------------------
__global__ __launch_bounds__(256, 2) void score_gemm(const float* __restrict__ X,
                                                     const float* __restrict__ Dm) {
    __shared__ float As[BK][BM + 4];
    __shared__ float Bs[BK][BN + 4];

    const int t  = threadIdx.x;
    const int m0 = blockIdx.y * BM;
    const int n0 = blockIdx.x * BN;
    const int ty = t >> 4;   // 0..15 (m dim)
    const int tx = t & 15;   // 0..15 (n dim)

    float acc[8][8];
#pragma unroll
    for (int i = 0; i < 8; i++)
#pragma unroll
        for (int j = 0; j < 8; j++) acc[i][j] = 0.f;

    for (int k0 = 0; k0 < DIM; k0 += BK) {
        // load X tile [BM x BK] -> As[k][m]
#pragma unroll
        for (int it = 0; it < 2; it++) {
            int li  = t + it * 256;          // 0..511 float4 slots
            int row = li >> 2;               // 0..127
            int c4  = li & 3;                // 0..3
            float4 v = *(const float4*)(X + (size_t)(m0 + row) * DIM + k0 + c4 * 4);
            As[c4 * 4 + 0][row] = v.x;
            As[c4 * 4 + 1][row] = v.y;
            As[c4 * 4 + 2][row] = v.z;
            As[c4 * 4 + 3][row] = v.w;
        }
        // load data tile [BN x BK] -> Bs[k][n]  (guard N tail)
#pragma unroll
        for (int it = 0; it < 2; it++) {
            int li  = t + it * 256;
            int row = li >> 2;
            int c4  = li & 3;
            int n   = n0 + row;
            float4 v = make_float4(0.f, 0.f, 0.f, 0.f);
            if (n < NDATA) v = *(const float4*)(Dm + (size_t)n * DIM + k0 + c4 * 4);
            Bs[c4 * 4 + 0][row] = v.x;
            Bs[c4 * 4 + 1][row] = v.y;
            Bs[c4 * 4 + 2][row] = v.z;
            Bs[c4 * 4 + 3][row] = v.w;
        }
        __syncthreads();

#pragma unroll
        for (int kk = 0; kk < BK; kk++) {
            float4 a0 = *(const float4*)&As[kk][ty * 8];
            float4 a1 = *(const float4*)&As[kk][ty * 8 + 4];
            float4 b0 = *(const float4*)&Bs[kk][tx * 8];
            float4 b1 = *(const float4*)&Bs[kk][tx * 8 + 4];
            float a[8] = {a0.x, a0.y, a0.z, a0.w, a1.x, a1.y, a1.z, a1.w};
            float b[8] = {b0.x, b0.y, b0.z, b0.w, b1.x, b1.y, b1.z, b1.w};
#pragma unroll
            for (int i = 0; i < 8; i++)
#pragma unroll
                for (int j = 0; j < 8; j++) acc[i][j] += a[i] * b[j];
        }
        __syncthreads();
    }

    // Epilogue: s = d2[n] - 2*acc
    const bool full = (n0 + BN <= NDATA);
    if (full) {
        float dd[8];
#pragma unroll
        for (int j = 0; j < 8; j++) dd[j] = g_d2[n0 + tx * 8 + j];
#pragma unroll
        for (int i = 0; i < 8; i++) {
            int m = m0 + ty * 8 + i;
            float* outp = g_scores + (size_t)m * NDATA + n0 + tx * 8;
            float4 s0, s1;
            s0.x = dd[0] - 2.f * acc[i][0];
            s0.y = dd[1] - 2.f * acc[i][1];
            s0.z = dd[2] - 2.f * acc[i][2];
            s0.w = dd[3] - 2.f * acc[i][3];
            s1.x = dd[4] - 2.f * acc[i][4];
            s1.y = dd[5] - 2.f * acc[i][5];
            s1.z = dd[6] - 2.f * acc[i][6];
            s1.w = dd[7] - 2.f * acc[i][7];
            *(float4*)(outp)     = s0;
            *(float4*)(outp + 4) = s1;
        }
    } else {
#pragma unroll
        for (int i = 0; i < 8; i++) {
            int m = m0 + ty * 8 + i;
#pragma unroll
            for (int j = 0; j < 8; j++) {
                int n = n0 + tx * 8 + j;
                if (n < NDATA)
                    g_scores[(size_t)m * NDATA + n] = g_d2[n] - 2.f * acc[i][j];
            }
        }
    }
}

// ---------------------------------------------------------------------------
// Kernel 3: per-query top-10 (smallest score, ties -> smaller index, matching
// lax.top_k), then mode of the 10 neighbor labels (ties -> smaller class,
// matching argmax over one-hot counts). One block per query.
// ---------------------------------------------------------------------------
__global__ void select_kernel(const void* __restrict__ targets_raw,
                              float* __restrict__ out) {
    const int q   = blockIdx.x;
    const int tid = threadIdx.x;
    const float* row = g_scores + (size_t)q * NDATA;

    const float FINF = 3.4e38f;
    float v[KNN];
    int   id[KNN];
#pragma unroll
    for (int i = 0; i < KNN; i++) { v[i] = FINF; id[i] = 0x7fffffff; }
    float worst = FINF;

    // Per-thread streaming top-10 (sorted ascending; strict '<' + monotone
    // indices keeps first-occurrence order on exact ties)
    for (int n = tid; n < NDATA; n += blockDim.x) {
        float s = row[n];
        if (s < worst) {
            v[KNN - 1] = s; id[KNN - 1] = n;
#pragma unroll
            for (int p = KNN - 1; p > 0; p--) {
                if (v[p] < v[p - 1]) {
                    float tv = v[p]; v[p] = v[p - 1]; v[p - 1] = tv;
                    int ti = id[p]; id[p] = id[p - 1]; id[p - 1] = ti;
                }
            }
            worst = v[KNN - 1];
        }
    }

    __shared__ float sv[256 * KNN];
    __shared__ int   si[256 * KNN];
    __shared__ float rv[256];
    __shared__ int   ri[256];
    __shared__ int   topIdx[KNN];
    __shared__ int   lab[KNN];

#pragma unroll
    for (int j = 0; j < KNN; j++) { sv[tid * KNN + j] = v[j]; si[tid * KNN + j] = id[j]; }
    __syncthreads();

    // 10 rounds of global argmin (value, then smaller index) over 2560 cands
    for (int r = 0; r < KNN; r++) {
        float bv = FINF; int bi = 0x7fffffff;
#pragma unroll
        for (int j = 0; j < KNN; j++) {
            float x = sv[tid * KNN + j];
            int  xi = si[tid * KNN + j];
            if (x < bv || (x == bv && xi < bi)) { bv = x; bi = xi; }
        }
        rv[tid] = bv; ri[tid] = bi;
        __syncthreads();
        for (int s2 = 128; s2 > 0; s2 >>= 1) {
            if (tid < s2) {
                float xv = rv[tid + s2]; int xi = ri[tid + s2];
                if (xv < rv[tid] || (xv == rv[tid] && xi < ri[tid])) {
                    rv[tid] = xv; ri[tid] = xi;
                }
            }
            __syncthreads();
        }
        int gb = ri[0];          // winner's data index (unique across threads)
        if (tid == 0) topIdx[r] = gb;
#pragma unroll
        for (int j = 0; j < KNN; j++)
            if (si[tid * KNN + j] == gb) sv[tid * KNN + j] = FINF;
        __syncthreads();
    }

    // Label fetch: dtype decided by device-side probe (int32 is the JAX
    // x64-disabled default; int64 supported via flag).
    if (tid < KNN) {
        int idx = topIdx[tid];
        int l;
        if (g_t64) l = (int)((const long long*)targets_raw)[idx];
        else       l = ((const int*)targets_raw)[idx];
        lab[tid] = l;
    }
    __syncthreads();

    if (tid == 0) {
        int bestLab = 1 << 30, bestC = 0;
#pragma unroll
        for (int i = 0; i < KNN; i++) {
            int li = lab[i], c = 0;
#pragma unroll
            for (int j = 0; j < KNN; j++) c += (lab[j] == li);
            if (c > bestC || (c == bestC && li < bestLab)) { bestC = c; bestLab = li; }
        }
        out[q] = (float)bestLab;
    }
}

// ---------------------------------------------------------------------------
extern "C" void kernel_launch(void* const* d_in, const int* in_sizes, int n_in,
                              void* d_out, int out_size) {
    // Robust input assignment by element count (order per metadata: X, data, targets)
    const float* X       = (const float*)d_in[0];   // 1024*512   = 524288
    const float* data    = (const float*)d_in[1];   // 50000*512  = 25600000
    const void*  targets = (const void*)d_in[2];    // 50000
    for (int i = 0; i < n_in && i < 3; i++) {
        if (in_sizes[i] == QN * DIM)          X       = (const float*)d_in[i];
        else if (in_sizes[i] == NDATA * DIM)  data    = (const float*)d_in[i];
        else if (in_sizes[i] == NDATA)        targets = (const void*)d_in[i];
    }
    float* out = (float*)d_out;
    (void)out_size;

    probe_targets<<<1, 32>>>(targets);

    d2_kernel<<<(NDATA * 32 + 255) / 256, 256>>>(data);

    dim3 g((NDATA + BN - 1) / BN, QN / BM);
    score_gemm<<<g, 256>>>(X, data);

    select_kernel<<<QN, 256>>>(targets, out);
}